// round 4
// baseline (speedup 1.0000x reference)
#include <cuda_runtime.h>

// ---------------- problem constants ----------------
static constexpr int NB    = 16;
static constexpr int CIN   = 64;
static constexpr int COUT  = 64;
static constexpr int HH    = 192;
static constexpr int WW    = 192;
static constexpr int HW    = HH * WW;          // 36864
static constexpr int HID   = 17;
static constexpr int KDY   = 4;
static constexpr int NGRP  = 8;
static constexpr float TEMP = 30.0f;
static constexpr float NEG_SLOPE = 0.01f;

// ---------------- device scratch (no allocations allowed) ----------------
__device__ float g_pooled[NB][CIN];
__device__ float g_attn[NB][KDY];
__device__ float g_filters[(size_t)NB * COUT * CIN * 9];   // 2.36 MB
__device__ float g_mean[NB * NGRP];
__device__ float g_rstd[NB * NGRP];

// ---------------- stage 1: global average pool (float4) ----------------
__global__ void pool_kernel(const float* __restrict__ x) {
    int bc = blockIdx.x;                       // 0..1023  (b*64 + c)
    const float4* p = (const float4*)(x + (size_t)bc * HW);
    float s = 0.f;
    for (int i = threadIdx.x; i < HW / 4; i += 256) {
        float4 v = p[i];
        s += (v.x + v.y) + (v.z + v.w);
    }
    __shared__ float sh[256];
    sh[threadIdx.x] = s;
    __syncthreads();
    for (int st = 128; st > 0; st >>= 1) {
        if (threadIdx.x < st) sh[threadIdx.x] += sh[threadIdx.x + st];
        __syncthreads();
    }
    if (threadIdx.x == 0) g_pooled[bc >> 6][bc & 63] = sh[0] * (1.0f / HW);
}

// ---------------- stage 2: attention MLP + softmax ----------------
__global__ void attn_kernel(const float* __restrict__ w1,
                            const float* __restrict__ w2,
                            const float* __restrict__ b2) {
    int b = threadIdx.x;
    if (b >= NB) return;
    float h[HID];
    #pragma unroll
    for (int j = 0; j < HID; j++) {
        float s = 0.f;
        for (int c = 0; c < CIN; c++) s += g_pooled[b][c] * w1[j * CIN + c];
        h[j] = fmaxf(s, 0.f);
    }
    float sc[KDY];
    float m = -1e30f;
    #pragma unroll
    for (int k = 0; k < KDY; k++) {
        float s = b2[k];
        for (int j = 0; j < HID; j++) s += h[j] * w2[k * HID + j];
        sc[k] = s / TEMP;
        m = fmaxf(m, sc[k]);
    }
    float tot = 0.f;
    #pragma unroll
    for (int k = 0; k < KDY; k++) { sc[k] = expf(sc[k] - m); tot += sc[k]; }
    #pragma unroll
    for (int k = 0; k < KDY; k++) g_attn[b][k] = sc[k] / tot;
}

// ---------------- stage 3: synthesize per-sample filters (float4) ----------------
// weights layout [K][COUT][CIN][3][3]; k-stride == COUT*CIN*9 == 36864 elements
__global__ void filter_kernel(const float* __restrict__ w) {
    const int PER4 = COUT * CIN * 9 / 4;       // 9216 float4 per sample
    int n = blockIdx.x * 256 + threadIdx.x;
    if (n >= NB * PER4) return;
    int b = n / PER4, r = n - b * PER4;
    float a0 = g_attn[b][0], a1 = g_attn[b][1], a2 = g_attn[b][2], a3 = g_attn[b][3];
    const float4* w4 = (const float4*)w;
    float4 v0 = w4[r], v1 = w4[PER4 + r], v2 = w4[2 * PER4 + r], v3 = w4[3 * PER4 + r];
    float4 o;
    o.x = a0 * v0.x + a1 * v1.x + a2 * v2.x + a3 * v3.x;
    o.y = a0 * v0.y + a1 * v1.y + a2 * v2.y + a3 * v3.y;
    o.z = a0 * v0.z + a1 * v1.z + a2 * v2.z + a3 * v3.z;
    o.w = a0 * v0.w + a1 * v1.w + a2 * v2.w + a3 * v3.w;
    ((float4*)g_filters)[n] = o;
}

// ---------------- stage 4: per-sample 3x3 conv (fp32, f32x2 FMA) ----------------
// Round-1 shape: 32x16 tile, 16 couts/block, 16-channel stages, 2 rows/thread.
// Only change vs R1: filter reads are LDS.128 (4 broadcasts/tap, was 8 LDS.64).
static constexpr int TW = 32;
static constexpr int TH = 16;
static constexpr int CHUNK = 16;
static constexpr int COB = 16;

typedef unsigned long long u64;

__device__ __forceinline__ u64 pack2(float v) {
    u64 r; unsigned u = __float_as_uint(v);
    asm("mov.b64 %0, {%1, %1};" : "=l"(r) : "r"(u));
    return r;
}
__device__ __forceinline__ void fma2(u64& d, u64 a, u64 b) {
    asm("fma.rn.f32x2 %0, %1, %2, %0;" : "+l"(d) : "l"(a), "l"(b));
}

__global__ __launch_bounds__(256) void conv_kernel(const float* __restrict__ x,
                                                   float* __restrict__ y) {
    __shared__ float sx[CHUNK][TH + 2][TW + 2];                 // 39168 B
    __shared__ __align__(16) float sf[CHUNK][9][COB];           //  9216 B
    const int b   = blockIdx.z >> 2;
    const int cob = (blockIdx.z & 3) * COB;
    const int h0 = blockIdx.y * TH, w0 = blockIdx.x * TW;
    const int tid = threadIdx.x, tx = tid & 31, ty = tid >> 5;  // ty 0..7
    const float* xb = x + (size_t)b * CIN * HW;

    u64 acc[16];
    #pragma unroll
    for (int i = 0; i < 16; i++) acc[i] = 0ull;

    for (int c0 = 0; c0 < CIN; c0 += CHUNK) {
        __syncthreads();
        // stage input tile (with halo, zero-padded)
        for (int i = tid; i < CHUNK * (TH + 2) * (TW + 2); i += 256) {
            int ci  = i / ((TH + 2) * (TW + 2));
            int rem = i - ci * ((TH + 2) * (TW + 2));
            int r = rem / (TW + 2), cc = rem - r * (TW + 2);
            int hh = h0 + r - 1, ww = w0 + cc - 1;
            float v = 0.f;
            if (hh >= 0 && hh < HH && ww >= 0 && ww < WW)
                v = xb[(size_t)(c0 + ci) * HW + hh * WW + ww];
            sx[ci][r][cc] = v;
        }
        // stage filters: sf[ci][tap][co]
        for (int i = tid; i < CHUNK * 9 * COB; i += 256) {
            int ci  = i / (9 * COB);
            int rem = i - ci * (9 * COB);
            int tap = rem / COB, co = rem - tap * COB;
            sf[ci][tap][co] =
                g_filters[(((size_t)b * COUT + cob + co) * CIN + (c0 + ci)) * 9 + tap];
        }
        __syncthreads();

        #pragma unroll 1
        for (int ci = 0; ci < CHUNK; ci++) {
            #pragma unroll
            for (int tap = 0; tap < 9; tap++) {
                const int kh = tap / 3, kw = tap % 3;
                u64 x0 = pack2(sx[ci][ty + kh][tx + kw]);
                u64 x1 = pack2(sx[ci][ty + 8 + kh][tx + kw]);
                const ulonglong2* fp = (const ulonglong2*)&sf[ci][tap][0];
                #pragma unroll
                for (int j = 0; j < 4; j++) {                  // LDS.128: couts 4j..4j+3
                    ulonglong2 f = fp[j];
                    fma2(acc[2 * j],         x0, f.x);
                    fma2(acc[2 * j + 1],     x0, f.y);
                    fma2(acc[8 + 2 * j],     x1, f.x);
                    fma2(acc[8 + 2 * j + 1], x1, f.y);
                }
            }
        }
    }

    size_t base = ((size_t)b * COUT + cob) * HW + (size_t)(h0 + ty) * WW + (w0 + tx);
    #pragma unroll
    for (int q = 0; q < 8; q++) {
        unsigned lo, hi;
        asm("mov.b64 {%0, %1}, %2;" : "=r"(lo), "=r"(hi) : "l"(acc[q]));
        y[base + (size_t)(2 * q) * HW]     = __uint_as_float(lo);
        y[base + (size_t)(2 * q + 1) * HW] = __uint_as_float(hi);
        asm("mov.b64 {%0, %1}, %2;" : "=r"(lo), "=r"(hi) : "l"(acc[8 + q]));
        y[base + (size_t)(2 * q) * HW + 8 * WW]     = __uint_as_float(lo);
        y[base + (size_t)(2 * q + 1) * HW + 8 * WW] = __uint_as_float(hi);
    }
}

// ---------------- stage 5a: GroupNorm statistics (float4, fp32 partials) ----------------
__global__ void gnstat_kernel(const float* __restrict__ y) {
    int bg = blockIdx.x;                        // b*8 + g, region is contiguous
    const float4* p = (const float4*)(y + (size_t)bg * 8 * HW);
    float s = 0.f, ss = 0.f;
    for (int i = threadIdx.x; i < 8 * HW / 4; i += 256) {
        float4 v = p[i];
        s  += (v.x + v.y) + (v.z + v.w);
        ss += (v.x * v.x + v.y * v.y) + (v.z * v.z + v.w * v.w);
    }
    __shared__ float sh1[256], sh2[256];
    sh1[threadIdx.x] = s; sh2[threadIdx.x] = ss;
    __syncthreads();
    for (int st = 128; st > 0; st >>= 1) {
        if (threadIdx.x < st) {
            sh1[threadIdx.x] += sh1[threadIdx.x + st];
            sh2[threadIdx.x] += sh2[threadIdx.x + st];
        }
        __syncthreads();
    }
    if (threadIdx.x == 0) {
        const double N = 8.0 * HW;
        double mean = (double)sh1[0] / N;
        double var  = (double)sh2[0] / N - mean * mean;
        g_mean[bg] = (float)mean;
        g_rstd[bg] = (float)rsqrt(var + 1e-5);
    }
}

// ---------------- stage 5b: normalize + affine + LeakyReLU (float4, div-free) ----------------
__global__ void norm_kernel(float* __restrict__ y,
                            const float* __restrict__ gamma,
                            const float* __restrict__ beta) {
    // grid: (HW/1024, NB*COUT); block 256; float4 per thread
    int bc = blockIdx.y;                        // b*64 + c
    int c  = bc & 63;
    int bg = bc >> 3;                           // b*8 + c/8
    float mu = g_mean[bg], rs = g_rstd[bg];
    float ga = gamma[c] * rs;
    float be = beta[c] - mu * ga;
    float4* p = (float4*)(y + (size_t)bc * HW) + blockIdx.x * 256 + threadIdx.x;
    float4 v = *p;
    v.x = fmaf(v.x, ga, be); v.x = v.x >= 0.f ? v.x : NEG_SLOPE * v.x;
    v.y = fmaf(v.y, ga, be); v.y = v.y >= 0.f ? v.y : NEG_SLOPE * v.y;
    v.z = fmaf(v.z, ga, be); v.z = v.z >= 0.f ? v.z : NEG_SLOPE * v.z;
    v.w = fmaf(v.w, ga, be); v.w = v.w >= 0.f ? v.w : NEG_SLOPE * v.w;
    *p = v;
}

// ---------------- launch ----------------
extern "C" void kernel_launch(void* const* d_in, const int* in_sizes, int n_in,
                              void* d_out, int out_size) {
    const float* x     = (const float*)d_in[0];
    const float* w1    = (const float*)d_in[1];
    const float* w2    = (const float*)d_in[2];
    const float* b2    = (const float*)d_in[3];
    const float* w     = (const float*)d_in[4];
    const float* gamma = (const float*)d_in[5];
    const float* beta  = (const float*)d_in[6];
    float* y = (float*)d_out;

    pool_kernel<<<NB * CIN, 256>>>(x);
    attn_kernel<<<1, 32>>>(w1, w2, b2);
    filter_kernel<<<(NB * COUT * CIN * 9 / 4 + 255) / 256, 256>>>(w);

    dim3 g(WW / TW, HH / TH, NB * 4);
    conv_kernel<<<g, 256>>>(x, y);

    gnstat_kernel<<<NB * NGRP, 256>>>(y);
    dim3 gn(HW / 1024, NB * COUT);
    norm_kernel<<<gn, 256>>>(y, gamma, beta);
}

// round 6
// speedup vs baseline: 2.0503x; 2.0503x over previous
#include <cuda_runtime.h>
#include <cuda_fp16.h>
#include <cstdint>

// ---------------- problem constants ----------------
static constexpr int NB    = 16;
static constexpr int CIN   = 64;
static constexpr int COUT  = 64;
static constexpr int HH    = 192;
static constexpr int WW    = 192;
static constexpr int HW    = HH * WW;          // 36864
static constexpr int HID   = 17;
static constexpr int KDY   = 4;
static constexpr int NGRP  = 8;
static constexpr float TEMP = 30.0f;
static constexpr float NEG_SLOPE = 0.01f;

// conv tiling: CTA = 1 sample x (4 rows x 96 cols) output, all 64 couts.
static constexpr int TROWS = 4;
static constexpr int TCOLS = 96;
static constexpr int SLAB_W   = TCOLS + 2;     // 98
static constexpr int SLAB_R   = TROWS + 2;     // 6
static constexpr int SLAB_PIX = SLAB_R * SLAB_W; // 588

// smem layout (bytes): x-slab hi, x-slab lo (128B per pixel = 64 fp16), filter double buffer
static constexpr int SMEM_SXH = 0;
static constexpr int SMEM_SXL = SLAB_PIX * 128;            // 75264
static constexpr int SMEM_SF  = 2 * SLAB_PIX * 128;        // 150528
static constexpr int CONV_SMEM = SMEM_SF + 2 * 16384;      // 183296

// ---------------- device scratch ----------------
__device__ float g_pooled[NB][CIN];
__device__ float g_attn[NB][KDY];
// filter fragments: [b][tap][kb(4)][m(4)][split(2)][lane(32)] x uint4  => 2.36 MB
__device__ uint4 g_ffrag4[NB * 9 * 1024];
__device__ float g_mean[NB * NGRP];
__device__ float g_rstd[NB * NGRP];

// ---------------- PTX helpers (portable: sm_80-era only) ----------------
__device__ __forceinline__ uint32_t smem_u32(const void* p) {
    uint32_t a;
    asm("{ .reg .u64 t; cvta.to.shared.u64 t, %1; cvt.u32.u64 %0, t; }" : "=r"(a) : "l"(p));
    return a;
}
__device__ __forceinline__ void ldsm_x4(uint32_t* r, uint32_t addr) {
    asm volatile("ldmatrix.sync.aligned.m8n8.x4.shared.b16 {%0,%1,%2,%3}, [%4];"
        : "=r"(r[0]), "=r"(r[1]), "=r"(r[2]), "=r"(r[3]) : "r"(addr));
}
__device__ __forceinline__ void mma16816(float* d, const uint32_t* a, const uint32_t* b) {
    asm volatile("mma.sync.aligned.m16n8k16.row.col.f32.f16.f16.f32 "
        "{%0,%1,%2,%3}, {%4,%5,%6,%7}, {%8,%9}, {%0,%1,%2,%3};"
        : "+f"(d[0]), "+f"(d[1]), "+f"(d[2]), "+f"(d[3])
        : "r"(a[0]), "r"(a[1]), "r"(a[2]), "r"(a[3]), "r"(b[0]), "r"(b[1]));
}
__device__ __forceinline__ uint32_t pack_h2(__half lo, __half hi) {
    return (uint32_t)__half_as_ushort(lo) | ((uint32_t)__half_as_ushort(hi) << 16);
}

// ---------------- stage 1: global average pool ----------------
__global__ void pool_kernel(const float* __restrict__ x) {
    int bc = blockIdx.x;
    const float4* p = (const float4*)(x + (size_t)bc * HW);
    float s = 0.f;
    for (int i = threadIdx.x; i < HW / 4; i += 256) {
        float4 v = p[i];
        s += (v.x + v.y) + (v.z + v.w);
    }
    __shared__ float sh[256];
    sh[threadIdx.x] = s;
    __syncthreads();
    for (int st = 128; st > 0; st >>= 1) {
        if (threadIdx.x < st) sh[threadIdx.x] += sh[threadIdx.x + st];
        __syncthreads();
    }
    if (threadIdx.x == 0) g_pooled[bc >> 6][bc & 63] = sh[0] * (1.0f / HW);
}

// ---------------- stage 2: attention MLP + softmax ----------------
__global__ void attn_kernel(const float* __restrict__ w1,
                            const float* __restrict__ w2,
                            const float* __restrict__ b2) {
    int b = threadIdx.x;
    if (b >= NB) return;
    float h[HID];
    #pragma unroll
    for (int j = 0; j < HID; j++) {
        float s = 0.f;
        for (int c = 0; c < CIN; c++) s += g_pooled[b][c] * w1[j * CIN + c];
        h[j] = fmaxf(s, 0.f);
    }
    float sc[KDY];
    float m = -1e30f;
    #pragma unroll
    for (int k = 0; k < KDY; k++) {
        float s = b2[k];
        for (int j = 0; j < HID; j++) s += h[j] * w2[k * HID + j];
        sc[k] = s / TEMP;
        m = fmaxf(m, sc[k]);
    }
    float tot = 0.f;
    #pragma unroll
    for (int k = 0; k < KDY; k++) { sc[k] = expf(sc[k] - m); tot += sc[k]; }
    #pragma unroll
    for (int k = 0; k < KDY; k++) g_attn[b][k] = sc[k] / tot;
}

// ---------------- stage 3: synthesize filters directly into mma A-fragment order ----------------
// Fragment A (m16n8k16 f16, row-major): lane = g*4+t (g=lane>>2, t=lane&3):
//   a0={F[o0][c0],F[o0][c0+1]} a1={F[o0+8][c0],..} a2={F[o0][c0+8],..} a3={F[o0+8][c0+8],..}
// where o0 = m*16+g, c0 = kb*16+2t.  split 0 = fp16(hi), split 1 = fp16(residual).
__global__ void filter_frag_kernel(const float* __restrict__ w) {
    int n = blockIdx.x * 256 + threadIdx.x;
    if (n >= NB * 9 * 1024) return;
    int lane = n & 31;
    int s    = (n >> 5) & 1;
    int m    = (n >> 6) & 3;
    int kb   = (n >> 8) & 3;
    int tap  = (n >> 10) % 9;
    int b    = n / (9 * 1024);
    float at0 = g_attn[b][0], at1 = g_attn[b][1], at2 = g_attn[b][2], at3 = g_attn[b][3];
    int g = lane >> 2, t2 = (lane & 3) * 2;
    int o0 = m * 16 + g;
    int c0 = kb * 16 + t2;
    uint32_t regs[4];
    #pragma unroll
    for (int rr = 0; rr < 4; ++rr) {
        int o = o0 + (rr & 1) * 8;
        int cA = c0 + (rr >> 1) * 8;
        float fv[2];
        #pragma unroll
        for (int e = 0; e < 2; ++e) {
            int c = cA + e;
            int base = (o * 64 + c) * 9 + tap;
            fv[e] = at0 * w[base] + at1 * w[base + 4096 * 9]
                  + at2 * w[base + 2 * 4096 * 9] + at3 * w[base + 3 * 4096 * 9];
        }
        __half h0 = __float2half_rn(fv[0]), h1 = __float2half_rn(fv[1]);
        if (s == 1) {
            h0 = __float2half_rn(fv[0] - __half2float(h0));
            h1 = __float2half_rn(fv[1] - __half2float(h1));
        }
        regs[rr] = pack_h2(h0, h1);
    }
    g_ffrag4[n] = make_uint4(regs[0], regs[1], regs[2], regs[3]);
}

// ---------------- stage 4: mma.sync fp16 3-chain conv ----------------
// 512 threads = 16 warps: warp = (m_half in {0,1}) x (nchunk in 0..7).
// nchunk -> (row = nchunk>>1, col-half = nchunk&1): warp tile = 32 couts x 48 px.
__global__ __launch_bounds__(512, 1) void conv_mma_kernel(const float* __restrict__ x,
                                                          float* __restrict__ y) {
    extern __shared__ char smem[];
    const uint32_t smem_base = smem_u32(smem);
    const int tid = threadIdx.x, lane = tid & 31, wid = tid >> 5;
    const int b  = blockIdx.z;
    const int h0 = blockIdx.y * TROWS;
    const int w0 = blockIdx.x * TCOLS;
    const float* xb = x + (size_t)b * CIN * HW;

    // ---- stage x slab: fp16 hi/lo, [pixel][cin], XOR-swizzled 16B chunks ----
    for (int idx = tid; idx < CIN * SLAB_PIX; idx += 512) {
        int c = idx / SLAB_PIX;
        int p = idx - c * SLAB_PIX;
        int r = p / SLAB_W, cc = p - r * SLAB_W;
        int hh = h0 + r - 1, ww = w0 + cc - 1;
        float v = 0.f;
        if (hh >= 0 && hh < HH && ww >= 0 && ww < WW)
            v = xb[(size_t)c * HW + hh * WW + ww];
        __half hi = __float2half_rn(v);
        __half lo = __float2half_rn(v - __half2float(hi));
        uint32_t off = (uint32_t)(p * 128 + (((c >> 3) ^ (p & 7)) << 4) + (c & 7) * 2);
        *(__half*)(smem + SMEM_SXH + off) = hi;
        *(__half*)(smem + SMEM_SXL + off) = lo;
    }
    // tap-0 filter fragments -> buffer 0
    uint4* sF = (uint4*)(smem + SMEM_SF);
    {
        const uint4* src = g_ffrag4 + (size_t)(b * 9) * 1024;
        sF[tid] = src[tid];
        sF[tid + 512] = src[tid + 512];
    }
    __syncthreads();

    const int m_half = wid & 1;
    const int nchunk = wid >> 1;
    const int row    = nchunk >> 1;
    const int chalf  = nchunk & 1;

    const int gsel = lane >> 3, l7 = lane & 7;
    const int pix_lane = (gsel >> 1) * 8 + l7;   // pixel offset within n16 chunk
    const int ch_lane  = gsel & 1;               // k8 half

    float acc[12][4];
    #pragma unroll
    for (int i = 0; i < 12; i++)
        #pragma unroll
        for (int j = 0; j < 4; j++) acc[i][j] = 0.f;

    #pragma unroll 1
    for (int tap = 0; tap < 9; ++tap) {
        uint4 pf0, pf1;
        if (tap < 8) {
            const uint4* nxt = g_ffrag4 + (size_t)(b * 9 + tap + 1) * 1024;
            pf0 = nxt[tid];
            pf1 = nxt[tid + 512];
        }
        const uint4* sFb = sF + (tap & 1) * 1024;
        const int dh = tap / 3 - 1, dw = tap % 3 - 1;
        const int prow0 = (row + 1 + dh) * SLAB_W + (chalf * 48 + 1 + dw);

        #pragma unroll
        for (int kb = 0; kb < 4; ++kb) {
            uint4 aH0 = sFb[((kb * 4 + m_half * 2 + 0) * 2 + 0) * 32 + lane];
            uint4 aH1 = sFb[((kb * 4 + m_half * 2 + 1) * 2 + 0) * 32 + lane];
            uint4 aL0 = sFb[((kb * 4 + m_half * 2 + 0) * 2 + 1) * 32 + lane];
            uint4 aL1 = sFb[((kb * 4 + m_half * 2 + 1) * 2 + 1) * 32 + lane];
            #pragma unroll
            for (int q = 0; q < 3; ++q) {
                int pix = prow0 + q * 16 + pix_lane;
                int chunk = kb * 2 + ch_lane;
                uint32_t off = (uint32_t)(pix * 128 + (((chunk ^ (pix & 7)) << 4)));
                uint32_t bh[4], bl[4];
                ldsm_x4(bh, smem_base + SMEM_SXH + off);
                ldsm_x4(bl, smem_base + SMEM_SXL + off);
                #pragma unroll
                for (int nn = 0; nn < 2; ++nn) {
                    int ai = q * 2 + nn;
                    // chains: xhi*fhi + xlo*fhi + xhi*flo
                    mma16816(acc[ai],     (const uint32_t*)&aH0, bh + 2 * nn);
                    mma16816(acc[ai],     (const uint32_t*)&aH0, bl + 2 * nn);
                    mma16816(acc[ai],     (const uint32_t*)&aL0, bh + 2 * nn);
                    mma16816(acc[6 + ai], (const uint32_t*)&aH1, bh + 2 * nn);
                    mma16816(acc[6 + ai], (const uint32_t*)&aH1, bl + 2 * nn);
                    mma16816(acc[6 + ai], (const uint32_t*)&aL1, bh + 2 * nn);
                }
            }
        }
        __syncthreads();
        if (tap < 8) {
            uint4* dst = sF + ((tap + 1) & 1) * 1024;
            dst[tid] = pf0;
            dst[tid + 512] = pf1;
            __syncthreads();
        }
    }

    // ---- epilogue: D[g][2t..], D[g+8][2t..] -> y ----
    {
        const int g = lane >> 2, t2 = (lane & 3) * 2;
        const int h = h0 + row;
        #pragma unroll
        for (int mi = 0; mi < 2; ++mi) {
            int cout = m_half * 32 + mi * 16 + g;
            float* yb = y + ((size_t)(b * 64 + cout)) * HW + (size_t)h * WW
                      + w0 + chalf * 48 + t2;
            #pragma unroll
            for (int ai = 0; ai < 6; ++ai) {
                float2 v0 = make_float2(acc[mi * 6 + ai][0], acc[mi * 6 + ai][1]);
                float2 v1 = make_float2(acc[mi * 6 + ai][2], acc[mi * 6 + ai][3]);
                *(float2*)(yb + ai * 8) = v0;
                *(float2*)(yb + ai * 8 + (size_t)8 * HW) = v1;
            }
        }
    }
}

// ---------------- stage 5a: GroupNorm statistics ----------------
__global__ void gnstat_kernel(const float* __restrict__ y) {
    int bg = blockIdx.x;
    const float4* p = (const float4*)(y + (size_t)bg * 8 * HW);
    float s = 0.f, ss = 0.f;
    for (int i = threadIdx.x; i < 8 * HW / 4; i += 256) {
        float4 v = p[i];
        s  += (v.x + v.y) + (v.z + v.w);
        ss += (v.x * v.x + v.y * v.y) + (v.z * v.z + v.w * v.w);
    }
    __shared__ float sh1[256], sh2[256];
    sh1[threadIdx.x] = s; sh2[threadIdx.x] = ss;
    __syncthreads();
    for (int st = 128; st > 0; st >>= 1) {
        if (threadIdx.x < st) {
            sh1[threadIdx.x] += sh1[threadIdx.x + st];
            sh2[threadIdx.x] += sh2[threadIdx.x + st];
        }
        __syncthreads();
    }
    if (threadIdx.x == 0) {
        const double N = 8.0 * HW;
        double mean = (double)sh1[0] / N;
        double var  = (double)sh2[0] / N - mean * mean;
        g_mean[bg] = (float)mean;
        g_rstd[bg] = (float)rsqrt(var + 1e-5);
    }
}

// ---------------- stage 5b: normalize + affine + LeakyReLU ----------------
__global__ void norm_kernel(float* __restrict__ y,
                            const float* __restrict__ gamma,
                            const float* __restrict__ beta) {
    int bc = blockIdx.y;
    int c  = bc & 63;
    int bg = bc >> 3;
    float mu = g_mean[bg], rs = g_rstd[bg];
    float ga = gamma[c] * rs;
    float be = beta[c] - mu * ga;
    float4* p = (float4*)(y + (size_t)bc * HW) + blockIdx.x * 256 + threadIdx.x;
    float4 v = *p;
    v.x = fmaf(v.x, ga, be); v.x = v.x >= 0.f ? v.x : NEG_SLOPE * v.x;
    v.y = fmaf(v.y, ga, be); v.y = v.y >= 0.f ? v.y : NEG_SLOPE * v.y;
    v.z = fmaf(v.z, ga, be); v.z = v.z >= 0.f ? v.z : NEG_SLOPE * v.z;
    v.w = fmaf(v.w, ga, be); v.w = v.w >= 0.f ? v.w : NEG_SLOPE * v.w;
    *p = v;
}

// ---------------- launch ----------------
extern "C" void kernel_launch(void* const* d_in, const int* in_sizes, int n_in,
                              void* d_out, int out_size) {
    const float* x     = (const float*)d_in[0];
    const float* w1    = (const float*)d_in[1];
    const float* w2    = (const float*)d_in[2];
    const float* b2    = (const float*)d_in[3];
    const float* w     = (const float*)d_in[4];
    const float* gamma = (const float*)d_in[5];
    const float* beta  = (const float*)d_in[6];
    float* y = (float*)d_out;

    cudaFuncSetAttribute(conv_mma_kernel,
                         cudaFuncAttributeMaxDynamicSharedMemorySize, CONV_SMEM);

    pool_kernel<<<NB * CIN, 256>>>(x);
    attn_kernel<<<1, 32>>>(w1, w2, b2);
    filter_frag_kernel<<<(NB * 9 * 1024 + 255) / 256, 256>>>(w);

    dim3 g(WW / TCOLS, HH / TROWS, NB);
    conv_mma_kernel<<<g, 512, CONV_SMEM>>>(x, y);

    gnstat_kernel<<<NB * NGRP, 256>>>(y);
    dim3 gn(HW / 1024, NB * COUT);
    norm_kernel<<<gn, 256>>>(y, gamma, beta);
}

// round 7
// speedup vs baseline: 2.4891x; 1.2140x over previous
#include <cuda_runtime.h>
#include <cuda_fp16.h>
#include <cstdint>

// ---------------- problem constants ----------------
static constexpr int NB    = 16;
static constexpr int CIN   = 64;
static constexpr int COUT  = 64;
static constexpr int HH    = 192;
static constexpr int WW    = 192;
static constexpr int HW    = HH * WW;          // 36864
static constexpr int HID   = 17;
static constexpr int KDY   = 4;
static constexpr int NGRP  = 8;
static constexpr float TEMP = 30.0f;
static constexpr float NEG_SLOPE = 0.01f;

// conv tiling: CTA = 1 sample x (4 rows x 96 cols) output, all 64 couts.
static constexpr int TROWS = 4;
static constexpr int TCOLS = 96;
static constexpr int SLAB_W   = TCOLS + 2;     // 98
static constexpr int SLAB_R   = TROWS + 2;     // 6
static constexpr int SLAB_PIX = SLAB_R * SLAB_W; // 588

// smem layout (bytes): x slab (fp16, 128B/pixel) + ALL 9 taps of filter fragments
static constexpr int SMEM_SXH = 0;
static constexpr int SMEM_SF  = SLAB_PIX * 128;            // 75264
static constexpr int CONV_SMEM = SMEM_SF + 9 * 16384;      // 222720

// ---------------- device scratch ----------------
__device__ float g_pooled[NB][CIN];
__device__ float g_attn[NB][KDY];
// filter fragments: [b][tap][kb(4)][m(4)][split(2)][lane(32)] x uint4  => 2.36 MB
__device__ uint4 g_ffrag4[NB * 9 * 1024];
__device__ float g_mean[NB * NGRP];
__device__ float g_rstd[NB * NGRP];

// ---------------- PTX helpers (portable: sm_80-era only) ----------------
__device__ __forceinline__ uint32_t smem_u32(const void* p) {
    uint32_t a;
    asm("{ .reg .u64 t; cvta.to.shared.u64 t, %1; cvt.u32.u64 %0, t; }" : "=r"(a) : "l"(p));
    return a;
}
__device__ __forceinline__ void ldsm_x4(uint32_t* r, uint32_t addr) {
    asm volatile("ldmatrix.sync.aligned.m8n8.x4.shared.b16 {%0,%1,%2,%3}, [%4];"
        : "=r"(r[0]), "=r"(r[1]), "=r"(r[2]), "=r"(r[3]) : "r"(addr));
}
__device__ __forceinline__ void mma16816(float* d, const uint32_t* a, const uint32_t* b) {
    asm volatile("mma.sync.aligned.m16n8k16.row.col.f32.f16.f16.f32 "
        "{%0,%1,%2,%3}, {%4,%5,%6,%7}, {%8,%9}, {%0,%1,%2,%3};"
        : "+f"(d[0]), "+f"(d[1]), "+f"(d[2]), "+f"(d[3])
        : "r"(a[0]), "r"(a[1]), "r"(a[2]), "r"(a[3]), "r"(b[0]), "r"(b[1]));
}
__device__ __forceinline__ uint32_t pack_h2(__half lo, __half hi) {
    return (uint32_t)__half_as_ushort(lo) | ((uint32_t)__half_as_ushort(hi) << 16);
}

// ---------------- stage 1: global average pool ----------------
__global__ void pool_kernel(const float* __restrict__ x) {
    int bc = blockIdx.x;
    const float4* p = (const float4*)(x + (size_t)bc * HW);
    float s = 0.f;
    for (int i = threadIdx.x; i < HW / 4; i += 256) {
        float4 v = p[i];
        s += (v.x + v.y) + (v.z + v.w);
    }
    __shared__ float sh[256];
    sh[threadIdx.x] = s;
    __syncthreads();
    for (int st = 128; st > 0; st >>= 1) {
        if (threadIdx.x < st) sh[threadIdx.x] += sh[threadIdx.x + st];
        __syncthreads();
    }
    if (threadIdx.x == 0) g_pooled[bc >> 6][bc & 63] = sh[0] * (1.0f / HW);
}

// ---------------- stage 2: attention MLP + softmax ----------------
__global__ void attn_kernel(const float* __restrict__ w1,
                            const float* __restrict__ w2,
                            const float* __restrict__ b2) {
    int b = threadIdx.x;
    if (b >= NB) return;
    float h[HID];
    #pragma unroll
    for (int j = 0; j < HID; j++) {
        float s = 0.f;
        for (int c = 0; c < CIN; c++) s += g_pooled[b][c] * w1[j * CIN + c];
        h[j] = fmaxf(s, 0.f);
    }
    float sc[KDY];
    float m = -1e30f;
    #pragma unroll
    for (int k = 0; k < KDY; k++) {
        float s = b2[k];
        for (int j = 0; j < HID; j++) s += h[j] * w2[k * HID + j];
        sc[k] = s / TEMP;
        m = fmaxf(m, sc[k]);
    }
    float tot = 0.f;
    #pragma unroll
    for (int k = 0; k < KDY; k++) { sc[k] = expf(sc[k] - m); tot += sc[k]; }
    #pragma unroll
    for (int k = 0; k < KDY; k++) g_attn[b][k] = sc[k] / tot;
}

// ---------------- stage 3: synthesize filters directly into mma A-fragment order ----------------
// Fragment A (m16n8k16 f16, row-major): lane = g*4+t (g=lane>>2, t=lane&3):
//   a0={F[o0][c0],F[o0][c0+1]} a1={F[o0+8][c0],..} a2={F[o0][c0+8],..} a3={F[o0+8][c0+8],..}
// where o0 = m*16+g, c0 = kb*16+2t.  split 0 = fp16(f); split 1 = fp16 residual.
__global__ void filter_frag_kernel(const float* __restrict__ w) {
    int n = blockIdx.x * 256 + threadIdx.x;
    if (n >= NB * 9 * 1024) return;
    int lane = n & 31;
    int s    = (n >> 5) & 1;
    int m    = (n >> 6) & 3;
    int kb   = (n >> 8) & 3;
    int tap  = (n >> 10) % 9;
    int b    = n / (9 * 1024);
    float at0 = g_attn[b][0], at1 = g_attn[b][1], at2 = g_attn[b][2], at3 = g_attn[b][3];
    int g = lane >> 2, t2 = (lane & 3) * 2;
    int o0 = m * 16 + g;
    int c0 = kb * 16 + t2;
    uint32_t regs[4];
    #pragma unroll
    for (int rr = 0; rr < 4; ++rr) {
        int o = o0 + (rr & 1) * 8;
        int cA = c0 + (rr >> 1) * 8;
        float fv[2];
        #pragma unroll
        for (int e = 0; e < 2; ++e) {
            int c = cA + e;
            int base = (o * 64 + c) * 9 + tap;
            fv[e] = at0 * w[base] + at1 * w[base + 4096 * 9]
                  + at2 * w[base + 2 * 4096 * 9] + at3 * w[base + 3 * 4096 * 9];
        }
        __half h0 = __float2half_rn(fv[0]), h1 = __float2half_rn(fv[1]);
        if (s == 1) {
            h0 = __float2half_rn(fv[0] - __half2float(h0));
            h1 = __float2half_rn(fv[1] - __half2float(h1));
        }
        regs[rr] = pack_h2(h0, h1);
    }
    g_ffrag4[n] = make_uint4(regs[0], regs[1], regs[2], regs[3]);
}

// ---------------- stage 4: mma.sync fp16 2-chain conv (x plain fp16, f = hi+lo) ----------------
// 512 threads = 16 warps: warp = (m_half in {0,1}) x (nchunk in 0..7).
// nchunk -> (row = nchunk>>1, col-half = nchunk&1): warp tile = 32 couts x 48 px.
__global__ __launch_bounds__(512, 1) void conv_mma_kernel(const float* __restrict__ x,
                                                          float* __restrict__ y) {
    extern __shared__ char smem[];
    const uint32_t smem_base = smem_u32(smem);
    const int tid = threadIdx.x, lane = tid & 31, wid = tid >> 5;
    const int b  = blockIdx.z;
    const int h0 = blockIdx.y * TROWS;
    const int w0 = blockIdx.x * TCOLS;
    const float* xb = x + (size_t)b * CIN * HW;

    // ---- stage x slab: fp16, [pixel][cin], XOR-swizzled 16B chunks ----
    for (int idx = tid; idx < CIN * SLAB_PIX; idx += 512) {
        int c = idx / SLAB_PIX;
        int p = idx - c * SLAB_PIX;
        int r = p / SLAB_W, cc = p - r * SLAB_W;
        int hh = h0 + r - 1, ww = w0 + cc - 1;
        float v = 0.f;
        if (hh >= 0 && hh < HH && ww >= 0 && ww < WW)
            v = xb[(size_t)c * HW + hh * WW + ww];
        uint32_t off = (uint32_t)(p * 128 + (((c >> 3) ^ (p & 7)) << 4) + (c & 7) * 2);
        *(__half*)(smem + SMEM_SXH + off) = __float2half_rn(v);
    }
    // ALL 9 taps of filter fragments -> smem (no double buffering, no mainloop syncs)
    uint4* sF = (uint4*)(smem + SMEM_SF);
    {
        const uint4* src = g_ffrag4 + (size_t)(b * 9) * 1024;
        #pragma unroll
        for (int it = 0; it < 18; ++it)
            sF[tid + it * 512] = src[tid + it * 512];
    }
    __syncthreads();

    const int m_half = wid & 1;
    const int nchunk = wid >> 1;
    const int row    = nchunk >> 1;
    const int chalf  = nchunk & 1;

    const int gsel = lane >> 3, l7 = lane & 7;
    const int pix_lane = (gsel >> 1) * 8 + l7;   // pixel offset within n16 chunk
    const int ch_lane  = gsel & 1;               // k8 half

    float acc[12][4];
    #pragma unroll
    for (int i = 0; i < 12; i++)
        #pragma unroll
        for (int j = 0; j < 4; j++) acc[i][j] = 0.f;

    #pragma unroll 1
    for (int tap = 0; tap < 9; ++tap) {
        const uint4* sFb = sF + tap * 1024;
        const int dh = tap / 3 - 1, dw = tap % 3 - 1;
        const int prow0 = (row + 1 + dh) * SLAB_W + (chalf * 48 + 1 + dw);

        #pragma unroll
        for (int kb = 0; kb < 4; ++kb) {
            uint4 aH0 = sFb[((kb * 4 + m_half * 2 + 0) * 2 + 0) * 32 + lane];
            uint4 aH1 = sFb[((kb * 4 + m_half * 2 + 1) * 2 + 0) * 32 + lane];
            uint4 aL0 = sFb[((kb * 4 + m_half * 2 + 0) * 2 + 1) * 32 + lane];
            uint4 aL1 = sFb[((kb * 4 + m_half * 2 + 1) * 2 + 1) * 32 + lane];
            uint32_t bh[3][4];
            #pragma unroll
            for (int q = 0; q < 3; ++q) {
                int pix = prow0 + q * 16 + pix_lane;
                int chunk = kb * 2 + ch_lane;
                uint32_t off = (uint32_t)(pix * 128 + ((chunk ^ (pix & 7)) << 4));
                ldsm_x4(bh[q], smem_base + SMEM_SXH + off);
            }
            // pass 1: x * f_hi   (each acc touched once; 12 independent MMAs)
            #pragma unroll
            for (int q = 0; q < 3; ++q)
                #pragma unroll
                for (int mi = 0; mi < 2; ++mi)
                    #pragma unroll
                    for (int nn = 0; nn < 2; ++nn)
                        mma16816(acc[q * 2 + nn + mi * 6],
                                 (const uint32_t*)(mi ? &aH1 : &aH0), bh[q] + 2 * nn);
            // pass 2: x * f_lo   (12-apart reuse distance)
            #pragma unroll
            for (int q = 0; q < 3; ++q)
                #pragma unroll
                for (int mi = 0; mi < 2; ++mi)
                    #pragma unroll
                    for (int nn = 0; nn < 2; ++nn)
                        mma16816(acc[q * 2 + nn + mi * 6],
                                 (const uint32_t*)(mi ? &aL1 : &aL0), bh[q] + 2 * nn);
        }
    }

    // ---- epilogue: D[g][2t..], D[g+8][2t..] -> y ----
    {
        const int g = lane >> 2, t2 = (lane & 3) * 2;
        const int h = h0 + row;
        #pragma unroll
        for (int mi = 0; mi < 2; ++mi) {
            int cout = m_half * 32 + mi * 16 + g;
            float* yb = y + ((size_t)(b * 64 + cout)) * HW + (size_t)h * WW
                      + w0 + chalf * 48 + t2;
            #pragma unroll
            for (int ai = 0; ai < 6; ++ai) {
                float2 v0 = make_float2(acc[mi * 6 + ai][0], acc[mi * 6 + ai][1]);
                float2 v1 = make_float2(acc[mi * 6 + ai][2], acc[mi * 6 + ai][3]);
                *(float2*)(yb + ai * 8) = v0;
                *(float2*)(yb + ai * 8 + (size_t)8 * HW) = v1;
            }
        }
    }
}

// ---------------- stage 5a: GroupNorm statistics ----------------
__global__ void gnstat_kernel(const float* __restrict__ y) {
    int bg = blockIdx.x;
    const float4* p = (const float4*)(y + (size_t)bg * 8 * HW);
    float s = 0.f, ss = 0.f;
    for (int i = threadIdx.x; i < 8 * HW / 4; i += 256) {
        float4 v = p[i];
        s  += (v.x + v.y) + (v.z + v.w);
        ss += (v.x * v.x + v.y * v.y) + (v.z * v.z + v.w * v.w);
    }
    __shared__ float sh1[256], sh2[256];
    sh1[threadIdx.x] = s; sh2[threadIdx.x] = ss;
    __syncthreads();
    for (int st = 128; st > 0; st >>= 1) {
        if (threadIdx.x < st) {
            sh1[threadIdx.x] += sh1[threadIdx.x + st];
            sh2[threadIdx.x] += sh2[threadIdx.x + st];
        }
        __syncthreads();
    }
    if (threadIdx.x == 0) {
        const double N = 8.0 * HW;
        double mean = (double)sh1[0] / N;
        double var  = (double)sh2[0] / N - mean * mean;
        g_mean[bg] = (float)mean;
        g_rstd[bg] = (float)rsqrt(var + 1e-5);
    }
}

// ---------------- stage 5b: normalize + affine + LeakyReLU ----------------
__global__ void norm_kernel(float* __restrict__ y,
                            const float* __restrict__ gamma,
                            const float* __restrict__ beta) {
    int bc = blockIdx.y;
    int c  = bc & 63;
    int bg = bc >> 3;
    float mu = g_mean[bg], rs = g_rstd[bg];
    float ga = gamma[c] * rs;
    float be = beta[c] - mu * ga;
    float4* p = (float4*)(y + (size_t)bc * HW) + blockIdx.x * 256 + threadIdx.x;
    float4 v = *p;
    v.x = fmaf(v.x, ga, be); v.x = v.x >= 0.f ? v.x : NEG_SLOPE * v.x;
    v.y = fmaf(v.y, ga, be); v.y = v.y >= 0.f ? v.y : NEG_SLOPE * v.y;
    v.z = fmaf(v.z, ga, be); v.z = v.z >= 0.f ? v.z : NEG_SLOPE * v.z;
    v.w = fmaf(v.w, ga, be); v.w = v.w >= 0.f ? v.w : NEG_SLOPE * v.w;
    *p = v;
}

// ---------------- launch ----------------
extern "C" void kernel_launch(void* const* d_in, const int* in_sizes, int n_in,
                              void* d_out, int out_size) {
    const float* x     = (const float*)d_in[0];
    const float* w1    = (const float*)d_in[1];
    const float* w2    = (const float*)d_in[2];
    const float* b2    = (const float*)d_in[3];
    const float* w     = (const float*)d_in[4];
    const float* gamma = (const float*)d_in[5];
    const float* beta  = (const float*)d_in[6];
    float* y = (float*)d_out;

    cudaFuncSetAttribute(conv_mma_kernel,
                         cudaFuncAttributeMaxDynamicSharedMemorySize, CONV_SMEM);

    pool_kernel<<<NB * CIN, 256>>>(x);
    attn_kernel<<<1, 32>>>(w1, w2, b2);
    filter_frag_kernel<<<(NB * 9 * 1024 + 255) / 256, 256>>>(w);

    dim3 g(WW / TCOLS, HH / TROWS, NB);
    conv_mma_kernel<<<g, 512, CONV_SMEM>>>(x, y);

    gnstat_kernel<<<NB * NGRP, 256>>>(y);
    dim3 gn(HW / 1024, NB * COUT);
    norm_kernel<<<gn, 256>>>(y, gamma, beta);
}

// round 8
// speedup vs baseline: 3.4542x; 1.3877x over previous
#include <cuda_runtime.h>
#include <cuda_fp16.h>
#include <cstdint>

// ---------------- problem constants ----------------
static constexpr int NB    = 16;
static constexpr int CIN   = 64;
static constexpr int COUT  = 64;
static constexpr int HH    = 192;
static constexpr int WW    = 192;
static constexpr int HW    = HH * WW;          // 36864
static constexpr int HID   = 17;
static constexpr int KDY   = 4;
static constexpr int NGRP  = 8;
static constexpr float TEMP = 30.0f;
static constexpr float NEG_SLOPE = 0.01f;

// conv tiling: CTA = 1 sample x (4 rows x 96 cols) output, all 64 couts.
static constexpr int TROWS = 4;
static constexpr int TCOLS = 96;
static constexpr int SLAB_W   = TCOLS + 2;     // 98
static constexpr int SLAB_R   = TROWS + 2;     // 6
static constexpr int SLAB_PIX = SLAB_R * SLAB_W; // 588

// smem layout (bytes): x slab (fp16, 128B/pixel) + ALL 9 taps of filter fragments (hi only)
static constexpr int SMEM_SXH = 0;
static constexpr int SMEM_SF  = SLAB_PIX * 128;            // 75264
static constexpr int CONV_SMEM = SMEM_SF + 9 * 8192;       // 148992

// ---------------- device scratch ----------------
__device__ float g_pooled[NB][CIN];
__device__ float g_attn[NB][KDY];
// filter fragments (single fp16): [b][tap][kb(4)][m(4)][lane(32)] x uint4 => 1.18 MB
__device__ uint4 g_ffrag4[NB * 9 * 512];
__device__ float g_part[NB * NGRP * 96 * 2];   // per-conv-CTA GN partials (sum, sumsq)
__device__ float g_mean[NB * NGRP];
__device__ float g_rstd[NB * NGRP];

// ---------------- PTX helpers (portable: sm_80-era only) ----------------
__device__ __forceinline__ uint32_t smem_u32(const void* p) {
    uint32_t a;
    asm("{ .reg .u64 t; cvta.to.shared.u64 t, %1; cvt.u32.u64 %0, t; }" : "=r"(a) : "l"(p));
    return a;
}
__device__ __forceinline__ void ldsm_x4(uint32_t* r, uint32_t addr) {
    asm volatile("ldmatrix.sync.aligned.m8n8.x4.shared.b16 {%0,%1,%2,%3}, [%4];"
        : "=r"(r[0]), "=r"(r[1]), "=r"(r[2]), "=r"(r[3]) : "r"(addr));
}
__device__ __forceinline__ void mma16816(float* d, const uint32_t* a, const uint32_t* b) {
    asm volatile("mma.sync.aligned.m16n8k16.row.col.f32.f16.f16.f32 "
        "{%0,%1,%2,%3}, {%4,%5,%6,%7}, {%8,%9}, {%0,%1,%2,%3};"
        : "+f"(d[0]), "+f"(d[1]), "+f"(d[2]), "+f"(d[3])
        : "r"(a[0]), "r"(a[1]), "r"(a[2]), "r"(a[3]), "r"(b[0]), "r"(b[1]));
}
__device__ __forceinline__ uint32_t pack_h2(__half lo, __half hi) {
    return (uint32_t)__half_as_ushort(lo) | ((uint32_t)__half_as_ushort(hi) << 16);
}

// ---------------- stage 1: global average pool ----------------
__global__ void pool_kernel(const float* __restrict__ x) {
    int bc = blockIdx.x;
    const float4* p = (const float4*)(x + (size_t)bc * HW);
    float s = 0.f;
    for (int i = threadIdx.x; i < HW / 4; i += 256) {
        float4 v = p[i];
        s += (v.x + v.y) + (v.z + v.w);
    }
    __shared__ float sh[256];
    sh[threadIdx.x] = s;
    __syncthreads();
    for (int st = 128; st > 0; st >>= 1) {
        if (threadIdx.x < st) sh[threadIdx.x] += sh[threadIdx.x + st];
        __syncthreads();
    }
    if (threadIdx.x == 0) g_pooled[bc >> 6][bc & 63] = sh[0] * (1.0f / HW);
}

// ---------------- stage 2: attention MLP + softmax ----------------
__global__ void attn_kernel(const float* __restrict__ w1,
                            const float* __restrict__ w2,
                            const float* __restrict__ b2) {
    int b = threadIdx.x;
    if (b >= NB) return;
    float h[HID];
    #pragma unroll
    for (int j = 0; j < HID; j++) {
        float s = 0.f;
        for (int c = 0; c < CIN; c++) s += g_pooled[b][c] * w1[j * CIN + c];
        h[j] = fmaxf(s, 0.f);
    }
    float sc[KDY];
    float m = -1e30f;
    #pragma unroll
    for (int k = 0; k < KDY; k++) {
        float s = b2[k];
        for (int j = 0; j < HID; j++) s += h[j] * w2[k * HID + j];
        sc[k] = s / TEMP;
        m = fmaxf(m, sc[k]);
    }
    float tot = 0.f;
    #pragma unroll
    for (int k = 0; k < KDY; k++) { sc[k] = expf(sc[k] - m); tot += sc[k]; }
    #pragma unroll
    for (int k = 0; k < KDY; k++) g_attn[b][k] = sc[k] / tot;
}

// ---------------- stage 3: synthesize filters directly into mma A-fragment order ----------------
// Fragment A (m16n8k16 f16, row-major): lane = g*4+t (g=lane>>2, t=lane&3):
//   a0={F[o0][c0],F[o0][c0+1]} a1={F[o0+8][c0],..} a2={F[o0][c0+8],..} a3={F[o0+8][c0+8],..}
// where o0 = m*16+g, c0 = kb*16+2t.  Single fp16 (no residual split).
__global__ void filter_frag_kernel(const float* __restrict__ w) {
    int n = blockIdx.x * 256 + threadIdx.x;
    if (n >= NB * 9 * 512) return;
    int lane = n & 31;
    int m    = (n >> 5) & 3;
    int kb   = (n >> 7) & 3;
    int tap  = (n >> 9) % 9;
    int b    = n / (9 * 512);
    float at0 = g_attn[b][0], at1 = g_attn[b][1], at2 = g_attn[b][2], at3 = g_attn[b][3];
    int g = lane >> 2, t2 = (lane & 3) * 2;
    int o0 = m * 16 + g;
    int c0 = kb * 16 + t2;
    uint32_t regs[4];
    #pragma unroll
    for (int rr = 0; rr < 4; ++rr) {
        int o = o0 + (rr & 1) * 8;
        int cA = c0 + (rr >> 1) * 8;
        float fv[2];
        #pragma unroll
        for (int e = 0; e < 2; ++e) {
            int c = cA + e;
            int base = (o * 64 + c) * 9 + tap;
            fv[e] = at0 * w[base] + at1 * w[base + 4096 * 9]
                  + at2 * w[base + 2 * 4096 * 9] + at3 * w[base + 3 * 4096 * 9];
        }
        regs[rr] = pack_h2(__float2half_rn(fv[0]), __float2half_rn(fv[1]));
    }
    g_ffrag4[n] = make_uint4(regs[0], regs[1], regs[2], regs[3]);
}

// ---------------- stage 4: mma.sync fp16 conv + fused GN partial stats ----------------
// 512 threads = 16 warps: warp = (m_half in {0,1}) x (nchunk in 0..7).
// nchunk -> (row = nchunk>>1, col-half = nchunk&1): warp tile = 32 couts x 48 px.
__global__ __launch_bounds__(512, 1) void conv_mma_kernel(const float* __restrict__ x,
                                                          float* __restrict__ y) {
    extern __shared__ char smem[];
    const uint32_t smem_base = smem_u32(smem);
    const int tid = threadIdx.x, lane = tid & 31, wid = tid >> 5;
    const int b  = blockIdx.z;
    const int h0 = blockIdx.y * TROWS;
    const int w0 = blockIdx.x * TCOLS;
    const float* xb = x + (size_t)b * CIN * HW;

    // ---- stage x slab: fp16, [pixel][cin], XOR-swizzled 16B chunks ----
    for (int idx = tid; idx < CIN * SLAB_PIX; idx += 512) {
        int c = idx / SLAB_PIX;
        int p = idx - c * SLAB_PIX;
        int r = p / SLAB_W, cc = p - r * SLAB_W;
        int hh = h0 + r - 1, ww = w0 + cc - 1;
        float v = 0.f;
        if (hh >= 0 && hh < HH && ww >= 0 && ww < WW)
            v = xb[(size_t)c * HW + hh * WW + ww];
        uint32_t off = (uint32_t)(p * 128 + (((c >> 3) ^ (p & 7)) << 4) + (c & 7) * 2);
        *(__half*)(smem + SMEM_SXH + off) = __float2half_rn(v);
    }
    // ALL 9 taps of filter fragments -> smem
    uint4* sF = (uint4*)(smem + SMEM_SF);
    {
        const uint4* src = g_ffrag4 + (size_t)(b * 9) * 512;
        #pragma unroll
        for (int it = 0; it < 9; ++it)
            sF[tid + it * 512] = src[tid + it * 512];
    }
    __syncthreads();

    const int m_half = wid & 1;
    const int nchunk = wid >> 1;
    const int row    = nchunk >> 1;
    const int chalf  = nchunk & 1;

    const int gsel = lane >> 3, l7 = lane & 7;
    const int pix_lane = (gsel >> 1) * 8 + l7;   // pixel offset within n16 chunk
    const int ch_lane  = gsel & 1;               // k8 half

    float acc[12][4];
    #pragma unroll
    for (int i = 0; i < 12; i++)
        #pragma unroll
        for (int j = 0; j < 4; j++) acc[i][j] = 0.f;

    #pragma unroll 1
    for (int tap = 0; tap < 9; ++tap) {
        const uint4* sFb = sF + tap * 512;
        const int dh = tap / 3 - 1, dw = tap % 3 - 1;
        const int prow0 = (row + 1 + dh) * SLAB_W + (chalf * 48 + 1 + dw);

        #pragma unroll
        for (int kb = 0; kb < 4; ++kb) {
            uint4 aH0 = sFb[(kb * 4 + m_half * 2 + 0) * 32 + lane];
            uint4 aH1 = sFb[(kb * 4 + m_half * 2 + 1) * 32 + lane];
            uint32_t bh[3][4];
            #pragma unroll
            for (int q = 0; q < 3; ++q) {
                int pix = prow0 + q * 16 + pix_lane;
                int chunk = kb * 2 + ch_lane;
                uint32_t off = (uint32_t)(pix * 128 + ((chunk ^ (pix & 7)) << 4));
                ldsm_x4(bh[q], smem_base + SMEM_SXH + off);
            }
            #pragma unroll
            for (int q = 0; q < 3; ++q)
                #pragma unroll
                for (int mi = 0; mi < 2; ++mi)
                    #pragma unroll
                    for (int nn = 0; nn < 2; ++nn)
                        mma16816(acc[q * 2 + nn + mi * 6],
                                 (const uint32_t*)(mi ? &aH1 : &aH0), bh[q] + 2 * nn);
        }
    }

    // ---- epilogue 1: write y ----
    {
        const int g = lane >> 2, t2 = (lane & 3) * 2;
        const int h = h0 + row;
        #pragma unroll
        for (int mi = 0; mi < 2; ++mi) {
            int cout = m_half * 32 + mi * 16 + g;
            float* yb = y + ((size_t)(b * 64 + cout)) * HW + (size_t)h * WW
                      + w0 + chalf * 48 + t2;
            #pragma unroll
            for (int ai = 0; ai < 6; ++ai) {
                float2 v0 = make_float2(acc[mi * 6 + ai][0], acc[mi * 6 + ai][1]);
                float2 v1 = make_float2(acc[mi * 6 + ai][2], acc[mi * 6 + ai][3]);
                *(float2*)(yb + ai * 8) = v0;
                *(float2*)(yb + ai * 8 + (size_t)8 * HW) = v1;
            }
        }
    }

    // ---- epilogue 2: GN partial stats (deterministic, no atomics) ----
    // thread's acc spans groups m_half*4 + {mi*2 + rowhalf}: ps[mi*4 + rowhalf*2 + stat]
    {
        float ps[8];
        #pragma unroll
        for (int j = 0; j < 8; ++j) ps[j] = 0.f;
        #pragma unroll
        for (int mi = 0; mi < 2; ++mi)
            #pragma unroll
            for (int ai = 0; ai < 6; ++ai) {
                float a0 = acc[mi * 6 + ai][0], a1 = acc[mi * 6 + ai][1];
                float a2 = acc[mi * 6 + ai][2], a3 = acc[mi * 6 + ai][3];
                ps[mi * 4 + 0] += a0 + a1;
                ps[mi * 4 + 1] += a0 * a0 + a1 * a1;
                ps[mi * 4 + 2] += a2 + a3;
                ps[mi * 4 + 3] += a2 * a2 + a3 * a3;
            }
        #pragma unroll
        for (int off = 16; off > 0; off >>= 1)
            #pragma unroll
            for (int j = 0; j < 8; ++j)
                ps[j] += __shfl_xor_sync(0xFFFFFFFFu, ps[j], off);

        __shared__ float sh_p[16][8];
        if (lane == 0)
            #pragma unroll
            for (int j = 0; j < 8; ++j) sh_p[wid][j] = ps[j];
        __syncthreads();

        if (tid < 16) {
            int mh = tid >> 3, j = tid & 7;
            float s = 0.f;
            #pragma unroll
            for (int w2 = 0; w2 < 16; ++w2)
                if ((w2 & 1) == mh) s += sh_p[w2][j];
            int group = mh * 4 + (j >> 1);
            int cta96 = blockIdx.y * 2 + blockIdx.x;
            g_part[((b * NGRP + group) * 96 + cta96) * 2 + (j & 1)] = s;
        }
    }
}

// ---------------- stage 5a: GN finalize (sum 96 partials per group) ----------------
__global__ void gnfin_kernel() {
    int bg = blockIdx.x;                        // 0..127
    int t = threadIdx.x;                        // 128
    __shared__ float s1[128], s2[128];
    float a = 0.f, c = 0.f;
    if (t < 96) {
        a = g_part[(bg * 96 + t) * 2];
        c = g_part[(bg * 96 + t) * 2 + 1];
    }
    s1[t] = a; s2[t] = c;
    __syncthreads();
    for (int st = 64; st > 0; st >>= 1) {
        if (t < st) { s1[t] += s1[t + st]; s2[t] += s2[t + st]; }
        __syncthreads();
    }
    if (t == 0) {
        const double N = 8.0 * HW;
        double mean = (double)s1[0] / N;
        double var  = (double)s2[0] / N - mean * mean;
        g_mean[bg] = (float)mean;
        g_rstd[bg] = (float)rsqrt(var + 1e-5);
    }
}

// ---------------- stage 5b: normalize + affine + LeakyReLU ----------------
__global__ void norm_kernel(float* __restrict__ y,
                            const float* __restrict__ gamma,
                            const float* __restrict__ beta) {
    int bc = blockIdx.y;
    int c  = bc & 63;
    int bg = bc >> 3;
    float mu = g_mean[bg], rs = g_rstd[bg];
    float ga = gamma[c] * rs;
    float be = beta[c] - mu * ga;
    float4* p = (float4*)(y + (size_t)bc * HW) + blockIdx.x * 256 + threadIdx.x;
    float4 v = *p;
    v.x = fmaf(v.x, ga, be); v.x = v.x >= 0.f ? v.x : NEG_SLOPE * v.x;
    v.y = fmaf(v.y, ga, be); v.y = v.y >= 0.f ? v.y : NEG_SLOPE * v.y;
    v.z = fmaf(v.z, ga, be); v.z = v.z >= 0.f ? v.z : NEG_SLOPE * v.z;
    v.w = fmaf(v.w, ga, be); v.w = v.w >= 0.f ? v.w : NEG_SLOPE * v.w;
    *p = v;
}

// ---------------- launch ----------------
extern "C" void kernel_launch(void* const* d_in, const int* in_sizes, int n_in,
                              void* d_out, int out_size) {
    const float* x     = (const float*)d_in[0];
    const float* w1    = (const float*)d_in[1];
    const float* w2    = (const float*)d_in[2];
    const float* b2    = (const float*)d_in[3];
    const float* w     = (const float*)d_in[4];
    const float* gamma = (const float*)d_in[5];
    const float* beta  = (const float*)d_in[6];
    float* y = (float*)d_out;

    cudaFuncSetAttribute(conv_mma_kernel,
                         cudaFuncAttributeMaxDynamicSharedMemorySize, CONV_SMEM);

    pool_kernel<<<NB * CIN, 256>>>(x);
    attn_kernel<<<1, 32>>>(w1, w2, b2);
    filter_frag_kernel<<<(NB * 9 * 512 + 255) / 256, 256>>>(w);

    dim3 g(WW / TCOLS, HH / TROWS, NB);
    conv_mma_kernel<<<g, 512, CONV_SMEM>>>(x, y);

    gnfin_kernel<<<NB * NGRP, 128>>>();
    dim3 gn(HW / 1024, NB * COUT);
    norm_kernel<<<gn, 256>>>(y, gamma, beta);
}

// round 9
// speedup vs baseline: 4.6112x; 1.3350x over previous
#include <cuda_runtime.h>
#include <cuda_fp16.h>
#include <cstdint>

// ---------------- problem constants ----------------
static constexpr int NB    = 16;
static constexpr int CIN   = 64;
static constexpr int COUT  = 64;
static constexpr int HH    = 192;
static constexpr int WW    = 192;
static constexpr int HW    = HH * WW;          // 36864
static constexpr int HID   = 17;
static constexpr int KDY   = 4;
static constexpr int NGRP  = 8;
static constexpr float TEMP = 30.0f;
static constexpr float NEG_SLOPE = 0.01f;

// conv tiling: CTA = 1 sample x (4 rows x 96 cols) output, all 64 couts.
static constexpr int TROWS = 4;
static constexpr int TCOLS = 96;
static constexpr int SLAB_W   = TCOLS + 2;     // 98
static constexpr int SLAB_R   = TROWS + 2;     // 6
static constexpr int SLAB_PIX = SLAB_R * SLAB_W; // 588

// smem layout (bytes): x slab (fp16, 128B/pixel) + ALL 9 taps of filter fragments
static constexpr int SMEM_SXH = 0;
static constexpr int SMEM_SF  = SLAB_PIX * 128;            // 75264
static constexpr int CONV_SMEM = SMEM_SF + 9 * 8192;       // 148992

// ---------------- device scratch ----------------
__device__ float g_pooled[NB][CIN];
__device__ float g_attn[NB][KDY];
__device__ float g_hsum[HH * NB * CIN];        // per-(h) pool partials [h][b*64+c]
__device__ __half g_xh[(size_t)NB * HH * WW * CIN];   // x as NHWC fp16 (75.5 MB)
// filter fragments (single fp16): [b][tap][kb(4)][m(4)][lane(32)] x uint4 => 1.18 MB
__device__ uint4 g_ffrag4[NB * 9 * 512];
__device__ float g_part[NB * NGRP * 96 * 2];   // per-conv-CTA GN partials (sum, sumsq)
__device__ float g_mean[NB * NGRP];
__device__ float g_rstd[NB * NGRP];

// ---------------- PTX helpers (portable: sm_80-era only) ----------------
__device__ __forceinline__ uint32_t smem_u32(const void* p) {
    uint32_t a;
    asm("{ .reg .u64 t; cvta.to.shared.u64 t, %1; cvt.u32.u64 %0, t; }" : "=r"(a) : "l"(p));
    return a;
}
__device__ __forceinline__ void ldsm_x4(uint32_t* r, uint32_t addr) {
    asm volatile("ldmatrix.sync.aligned.m8n8.x4.shared.b16 {%0,%1,%2,%3}, [%4];"
        : "=r"(r[0]), "=r"(r[1]), "=r"(r[2]), "=r"(r[3]) : "r"(addr));
}
__device__ __forceinline__ void mma16816(float* d, const uint32_t* a, const uint32_t* b) {
    asm volatile("mma.sync.aligned.m16n8k16.row.col.f32.f16.f16.f32 "
        "{%0,%1,%2,%3}, {%4,%5,%6,%7}, {%8,%9}, {%0,%1,%2,%3};"
        : "+f"(d[0]), "+f"(d[1]), "+f"(d[2]), "+f"(d[3])
        : "r"(a[0]), "r"(a[1]), "r"(a[2]), "r"(a[3]), "r"(b[0]), "r"(b[1]));
}
__device__ __forceinline__ uint32_t pack_h2(__half lo, __half hi) {
    return (uint32_t)__half_as_ushort(lo) | ((uint32_t)__half_as_ushort(hi) << 16);
}
__device__ __forceinline__ void cp_async16(uint32_t dst, const void* src, uint32_t sz) {
    asm volatile("cp.async.cg.shared.global [%0], [%1], 16, %2;"
                 :: "r"(dst), "l"(src), "r"(sz) : "memory");
}
__device__ __forceinline__ void cp_commit_wait() {
    asm volatile("cp.async.commit_group;" ::: "memory");
    asm volatile("cp.async.wait_group 0;" ::: "memory");
}

// ---------------- stage 0: NCHW f32 -> NHWC fp16 transpose + pool partials ----------------
// grid (HH, NB), 256 threads. smem tile [w][c] fp16 with 16B-granule XOR swizzle.
__global__ void prep_kernel(const float* __restrict__ x) {
    const int h = blockIdx.x, b = blockIdx.y;
    __shared__ __align__(16) char st[WW * 128];      // 24576 B
    const int tid = threadIdx.x;

    for (int i = tid; i < CIN * WW; i += 256) {
        int c = i / WW, w = i - c * WW;               // consecutive tid -> consecutive w
        float v = x[(((size_t)b * CIN + c) * HH + h) * WW + w];
        uint32_t off = (uint32_t)(w * 128 + (((c >> 3) ^ (w & 7)) << 4) + (c & 7) * 2);
        *(__half*)(st + off) = __float2half_rn(v);
    }
    __syncthreads();

    if (tid < CIN) {
        int c = tid, gr = c >> 3, c7 = (c & 7) * 2;
        float s = 0.f;
        for (int w = 0; w < WW; ++w)
            s += __half2float(*(const __half*)(st + w * 128 + ((gr ^ (w & 7)) << 4) + c7));
        g_hsum[h * (NB * CIN) + b * CIN + c] = s;
    }

    uint4* dst = (uint4*)(g_xh + ((size_t)(b * HH + h) * WW) * CIN);
    for (int i = tid; i < WW * 8; i += 256) {
        int w = i >> 3, c8 = i & 7;
        uint32_t off = (uint32_t)(w * 128 + ((c8 ^ (w & 7)) << 4));
        dst[i] = *(const uint4*)(st + off);
    }
}

// ---------------- stage 1: finalize pool ----------------
__global__ void pool2_kernel() {     // grid 4, 256 threads
    int bc = blockIdx.x * 256 + threadIdx.x;      // 0..1023
    float s = 0.f;
    for (int h = 0; h < HH; ++h) s += g_hsum[h * (NB * CIN) + bc];
    g_pooled[bc >> 6][bc & 63] = s * (1.0f / HW);
}

// ---------------- stage 2: attention MLP + softmax ----------------
__global__ void attn_kernel(const float* __restrict__ w1,
                            const float* __restrict__ w2,
                            const float* __restrict__ b2) {
    int b = threadIdx.x;
    if (b >= NB) return;
    float h[HID];
    #pragma unroll
    for (int j = 0; j < HID; j++) {
        float s = 0.f;
        for (int c = 0; c < CIN; c++) s += g_pooled[b][c] * w1[j * CIN + c];
        h[j] = fmaxf(s, 0.f);
    }
    float sc[KDY];
    float m = -1e30f;
    #pragma unroll
    for (int k = 0; k < KDY; k++) {
        float s = b2[k];
        for (int j = 0; j < HID; j++) s += h[j] * w2[k * HID + j];
        sc[k] = s / TEMP;
        m = fmaxf(m, sc[k]);
    }
    float tot = 0.f;
    #pragma unroll
    for (int k = 0; k < KDY; k++) { sc[k] = expf(sc[k] - m); tot += sc[k]; }
    #pragma unroll
    for (int k = 0; k < KDY; k++) g_attn[b][k] = sc[k] / tot;
}

// ---------------- stage 3: synthesize filters directly into mma A-fragment order ----------------
__global__ void filter_frag_kernel(const float* __restrict__ w) {
    int n = blockIdx.x * 256 + threadIdx.x;
    if (n >= NB * 9 * 512) return;
    int lane = n & 31;
    int m    = (n >> 5) & 3;
    int kb   = (n >> 7) & 3;
    int tap  = (n >> 9) % 9;
    int b    = n / (9 * 512);
    float at0 = g_attn[b][0], at1 = g_attn[b][1], at2 = g_attn[b][2], at3 = g_attn[b][3];
    int g = lane >> 2, t2 = (lane & 3) * 2;
    int o0 = m * 16 + g;
    int c0 = kb * 16 + t2;
    uint32_t regs[4];
    #pragma unroll
    for (int rr = 0; rr < 4; ++rr) {
        int o = o0 + (rr & 1) * 8;
        int cA = c0 + (rr >> 1) * 8;
        float fv[2];
        #pragma unroll
        for (int e = 0; e < 2; ++e) {
            int c = cA + e;
            int base = (o * 64 + c) * 9 + tap;
            fv[e] = at0 * w[base] + at1 * w[base + 4096 * 9]
                  + at2 * w[base + 2 * 4096 * 9] + at3 * w[base + 3 * 4096 * 9];
        }
        regs[rr] = pack_h2(__float2half_rn(fv[0]), __float2half_rn(fv[1]));
    }
    g_ffrag4[n] = make_uint4(regs[0], regs[1], regs[2], regs[3]);
}

// ---------------- stage 4: mma.sync fp16 conv + fused GN partial stats ----------------
__global__ __launch_bounds__(512, 1) void conv_mma_kernel(float* __restrict__ y) {
    extern __shared__ char smem[];
    const uint32_t smem_base = smem_u32(smem);
    const int tid = threadIdx.x, lane = tid & 31, wid = tid >> 5;
    const int b  = blockIdx.z;
    const int h0 = blockIdx.y * TROWS;
    const int w0 = blockIdx.x * TCOLS;

    // ---- stage x slab via cp.async from NHWC fp16 (zfill for halo) ----
    {
        const __half* xhb = g_xh + (size_t)b * HH * WW * CIN;
        for (int e = tid; e < SLAB_PIX * 8; e += 512) {
            int pix = e >> 3, ch = e & 7;
            int r = pix / SLAB_W, cc = pix - r * SLAB_W;
            int hh = h0 + r - 1, ww = w0 + cc - 1;
            bool ok = (hh >= 0) && (hh < HH) && (ww >= 0) && (ww < WW);
            uint32_t dst = smem_base + SMEM_SXH
                         + (uint32_t)(pix * 128 + ((ch ^ (pix & 7)) << 4));
            const void* src = ok
                ? (const void*)(xhb + ((size_t)hh * WW + ww) * CIN + ch * 8)
                : (const void*)xhb;
            cp_async16(dst, src, ok ? 16u : 0u);
        }
        // all 9 taps of filter fragments
        const uint4* src = g_ffrag4 + (size_t)(b * 9) * 512;
        for (int e = tid; e < 9 * 512; e += 512)
            cp_async16(smem_base + SMEM_SF + e * 16, src + e, 16u);
    }
    cp_commit_wait();
    __syncthreads();

    const int m_half = wid & 1;
    const int nchunk = wid >> 1;
    const int row    = nchunk >> 1;
    const int chalf  = nchunk & 1;

    const int gsel = lane >> 3, l7 = lane & 7;
    const int pix_lane = (gsel >> 1) * 8 + l7;   // pixel offset within n16 chunk
    const int ch_lane  = gsel & 1;               // k8 half

    const uint4* sF = (const uint4*)(smem + SMEM_SF);

    float acc[12][4];
    #pragma unroll
    for (int i = 0; i < 12; i++)
        #pragma unroll
        for (int j = 0; j < 4; j++) acc[i][j] = 0.f;

    #pragma unroll 1
    for (int tap = 0; tap < 9; ++tap) {
        const uint4* sFb = sF + tap * 512;
        const int dh = tap / 3 - 1, dw = tap % 3 - 1;
        const int prow0 = (row + 1 + dh) * SLAB_W + (chalf * 48 + 1 + dw);

        #pragma unroll
        for (int kb = 0; kb < 4; ++kb) {
            uint4 aH0 = sFb[(kb * 4 + m_half * 2 + 0) * 32 + lane];
            uint4 aH1 = sFb[(kb * 4 + m_half * 2 + 1) * 32 + lane];
            uint32_t bh[3][4];
            #pragma unroll
            for (int q = 0; q < 3; ++q) {
                int pix = prow0 + q * 16 + pix_lane;
                int chunk = kb * 2 + ch_lane;
                uint32_t off = (uint32_t)(pix * 128 + ((chunk ^ (pix & 7)) << 4));
                ldsm_x4(bh[q], smem_base + SMEM_SXH + off);
            }
            #pragma unroll
            for (int q = 0; q < 3; ++q)
                #pragma unroll
                for (int mi = 0; mi < 2; ++mi)
                    #pragma unroll
                    for (int nn = 0; nn < 2; ++nn)
                        mma16816(acc[q * 2 + nn + mi * 6],
                                 (const uint32_t*)(mi ? &aH1 : &aH0), bh[q] + 2 * nn);
        }
    }

    // ---- epilogue 1: write y ----
    {
        const int g = lane >> 2, t2 = (lane & 3) * 2;
        const int h = h0 + row;
        #pragma unroll
        for (int mi = 0; mi < 2; ++mi) {
            int cout = m_half * 32 + mi * 16 + g;
            float* yb = y + ((size_t)(b * 64 + cout)) * HW + (size_t)h * WW
                      + w0 + chalf * 48 + t2;
            #pragma unroll
            for (int ai = 0; ai < 6; ++ai) {
                float2 v0 = make_float2(acc[mi * 6 + ai][0], acc[mi * 6 + ai][1]);
                float2 v1 = make_float2(acc[mi * 6 + ai][2], acc[mi * 6 + ai][3]);
                *(float2*)(yb + ai * 8) = v0;
                *(float2*)(yb + ai * 8 + (size_t)8 * HW) = v1;
            }
        }
    }

    // ---- epilogue 2: GN partial stats (deterministic, no atomics) ----
    {
        float ps[8];
        #pragma unroll
        for (int j = 0; j < 8; ++j) ps[j] = 0.f;
        #pragma unroll
        for (int mi = 0; mi < 2; ++mi)
            #pragma unroll
            for (int ai = 0; ai < 6; ++ai) {
                float a0 = acc[mi * 6 + ai][0], a1 = acc[mi * 6 + ai][1];
                float a2 = acc[mi * 6 + ai][2], a3 = acc[mi * 6 + ai][3];
                ps[mi * 4 + 0] += a0 + a1;
                ps[mi * 4 + 1] += a0 * a0 + a1 * a1;
                ps[mi * 4 + 2] += a2 + a3;
                ps[mi * 4 + 3] += a2 * a2 + a3 * a3;
            }
        #pragma unroll
        for (int off = 16; off > 0; off >>= 1)
            #pragma unroll
            for (int j = 0; j < 8; ++j)
                ps[j] += __shfl_xor_sync(0xFFFFFFFFu, ps[j], off);

        __shared__ float sh_p[16][8];
        if (lane == 0)
            #pragma unroll
            for (int j = 0; j < 8; ++j) sh_p[wid][j] = ps[j];
        __syncthreads();

        if (tid < 16) {
            int mh = tid >> 3, j = tid & 7;
            float s = 0.f;
            #pragma unroll
            for (int w2 = 0; w2 < 16; ++w2)
                if ((w2 & 1) == mh) s += sh_p[w2][j];
            int group = mh * 4 + (j >> 1);
            int cta96 = blockIdx.y * 2 + blockIdx.x;
            g_part[((b * NGRP + group) * 96 + cta96) * 2 + (j & 1)] = s;
        }
    }
}

// ---------------- stage 5a: GN finalize (sum 96 partials per group) ----------------
__global__ void gnfin_kernel() {
    int bg = blockIdx.x;                        // 0..127
    int t = threadIdx.x;                        // 128
    __shared__ float s1[128], s2[128];
    float a = 0.f, c = 0.f;
    if (t < 96) {
        a = g_part[(bg * 96 + t) * 2];
        c = g_part[(bg * 96 + t) * 2 + 1];
    }
    s1[t] = a; s2[t] = c;
    __syncthreads();
    for (int st = 64; st > 0; st >>= 1) {
        if (t < st) { s1[t] += s1[t + st]; s2[t] += s2[t + st]; }
        __syncthreads();
    }
    if (t == 0) {
        const double N = 8.0 * HW;
        double mean = (double)s1[0] / N;
        double var  = (double)s2[0] / N - mean * mean;
        g_mean[bg] = (float)mean;
        g_rstd[bg] = (float)rsqrt(var + 1e-5);
    }
}

// ---------------- stage 5b: normalize + affine + LeakyReLU ----------------
__global__ void norm_kernel(float* __restrict__ y,
                            const float* __restrict__ gamma,
                            const float* __restrict__ beta) {
    int bc = blockIdx.y;
    int c  = bc & 63;
    int bg = bc >> 3;
    float mu = g_mean[bg], rs = g_rstd[bg];
    float ga = gamma[c] * rs;
    float be = beta[c] - mu * ga;
    float4* p = (float4*)(y + (size_t)bc * HW) + blockIdx.x * 256 + threadIdx.x;
    float4 v = *p;
    v.x = fmaf(v.x, ga, be); v.x = v.x >= 0.f ? v.x : NEG_SLOPE * v.x;
    v.y = fmaf(v.y, ga, be); v.y = v.y >= 0.f ? v.y : NEG_SLOPE * v.y;
    v.z = fmaf(v.z, ga, be); v.z = v.z >= 0.f ? v.z : NEG_SLOPE * v.z;
    v.w = fmaf(v.w, ga, be); v.w = v.w >= 0.f ? v.w : NEG_SLOPE * v.w;
    *p = v;
}

// ---------------- launch ----------------
extern "C" void kernel_launch(void* const* d_in, const int* in_sizes, int n_in,
                              void* d_out, int out_size) {
    const float* x     = (const float*)d_in[0];
    const float* w1    = (const float*)d_in[1];
    const float* w2    = (const float*)d_in[2];
    const float* b2    = (const float*)d_in[3];
    const float* w     = (const float*)d_in[4];
    const float* gamma = (const float*)d_in[5];
    const float* beta  = (const float*)d_in[6];
    float* y = (float*)d_out;

    cudaFuncSetAttribute(conv_mma_kernel,
                         cudaFuncAttributeMaxDynamicSharedMemorySize, CONV_SMEM);

    prep_kernel<<<dim3(HH, NB), 256>>>(x);
    pool2_kernel<<<4, 256>>>();
    attn_kernel<<<1, 32>>>(w1, w2, b2);
    filter_frag_kernel<<<(NB * 9 * 512 + 255) / 256, 256>>>(w);

    dim3 g(WW / TCOLS, HH / TROWS, NB);
    conv_mma_kernel<<<g, 512, CONV_SMEM>>>(y);

    gnfin_kernel<<<NB * NGRP, 128>>>();
    dim3 gn(HW / 1024, NB * COUT);
    norm_kernel<<<gn, 256>>>(y, gamma, beta);
}